// round 11
// baseline (speedup 1.0000x reference)
#include <cuda_runtime.h>
#include <cuda_bf16.h>
#include <cstdint>

// ---------------- problem dims (fixed by dataset) ----------------
#define T_STEPS 512
#define BATCH   128
#define SDIM    1024
#define ODIM    256
#define JDIM    (SDIM + ODIM)   // 1280

// ---------------- tiling: group == cluster ----------------
#define NGRP 8               // batch groups (independent recurrences)
#define GR   16              // batch rows per group
#define NJT  16              // j tiles per group == cluster size
#define JT   80              // j cols per CTA
#define NCTAS (NGRP * NJT)   // 128 CTAs
#define NTHREADS 256
#define NWARPS 8
#define KSLICE 128           // K slice per warp (split-K over 8 warps)
#define CLUSTER 16
#define NPRODUCERS 13        // jtiles 0..12 produce h columns (j0 < 1024)
#define PAD 8
#define GSTRIDE (SDIM + PAD) // 1032 halves per smem row (516 words: conflict-free)
#define ROW_BYTES (SDIM * 2) // 2048 B per G row in gmem
#define WROWS 40             // smem-resident W rows (cols j0+40 .. j0+79)
#define EPT 5                // epilogue elements per thread (16*80/256)

// smem layout (bytes)
#define SG_BYTES (GR * GSTRIDE * 2)        // 33024
#define SW_BYTES (WROWS * GSTRIDE * 2)     // 82560
#define SP_BYTES (NWARPS * GR * JT * 4)    // 40960
#define SMEM_TOTAL (SG_BYTES + SW_BYTES + SP_BYTES + 32)  // + 3 mbarriers

// ---------------- device globals ----------------
__device__ __align__(16) __nv_bfloat16 g_W[(size_t)JDIM * SDIM];      // concat(w_r,w_o) bf16
__device__ __align__(16) __nv_bfloat16 g_G[2][(size_t)BATCH * SDIM];  // tanh(h), double-buffered

// ---------------- helpers ----------------
__device__ __forceinline__ float tanh_fast(float v) {
    float r;
    asm("tanh.approx.f32 %0, %1;" : "=f"(r) : "f"(v));
    return r;
}
__device__ __forceinline__ void mma16816(float c[4], const unsigned a[4],
                                         unsigned b0, unsigned b1) {
    asm volatile(
        "mma.sync.aligned.m16n8k16.row.col.f32.bf16.bf16.f32 "
        "{%0,%1,%2,%3}, {%4,%5,%6,%7}, {%8,%9}, {%0,%1,%2,%3};\n"
        : "+f"(c[0]), "+f"(c[1]), "+f"(c[2]), "+f"(c[3])
        : "r"(a[0]), "r"(a[1]), "r"(a[2]), "r"(a[3]), "r"(b0), "r"(b1));
}
__device__ __forceinline__ void ldsm_x4(unsigned a[4], uint32_t addr) {
    asm volatile("ldmatrix.sync.aligned.m8n8.x4.shared.b16 {%0,%1,%2,%3}, [%4];"
                 : "=r"(a[0]), "=r"(a[1]), "=r"(a[2]), "=r"(a[3]) : "r"(addr));
}
// local wait (TMA smem delivery): cta-scope acquire
__device__ __forceinline__ void mbar_wait(uint32_t mbar, unsigned parity) {
    asm volatile(
        "{\n\t"
        ".reg .pred P;\n\t"
        "WL_%=:\n\t"
        "mbarrier.try_wait.parity.acquire.cta.shared::cta.b64 P, [%0], %1, 0x989680;\n\t"
        "@P bra.uni WD_%=;\n\t"
        "bra.uni WL_%=;\n\t"
        "WD_%=:\n\t"
        "}" :: "r"(mbar), "r"(parity) : "memory");
}
// cross-CTA wait (gmem data / smem-free signals from peers): cluster-scope acquire
__device__ __forceinline__ void mbar_wait_cl(uint32_t mbar, unsigned parity) {
    asm volatile(
        "{\n\t"
        ".reg .pred P;\n\t"
        "WL_%=:\n\t"
        "mbarrier.try_wait.parity.acquire.cluster.shared::cta.b64 P, [%0], %1, 0x989680;\n\t"
        "@P bra.uni WD_%=;\n\t"
        "bra.uni WL_%=;\n\t"
        "WD_%=:\n\t"
        "}" :: "r"(mbar), "r"(parity) : "memory");
}
// remote arrive with release.cluster (orders prior gmem/smem ops for cluster observers)
__device__ __forceinline__ void mbar_arrive_remote(uint32_t local_addr, uint32_t target_rank) {
    asm volatile(
        "{\n\t"
        ".reg .b32 ra;\n\t"
        "mapa.shared::cluster.u32 ra, %0, %1;\n\t"
        "mbarrier.arrive.release.cluster.shared::cluster.b64 _, [ra];\n\t"
        "}" :: "r"(local_addr), "r"(target_rank) : "memory");
}

// ---------------- init: bf16 weights + G0 = tanh(h_init) ----------------
__global__ void trnn_init(const float* __restrict__ w_r, const float* __restrict__ w_o,
                          const float* __restrict__ h_init) {
    size_t stride = (size_t)gridDim.x * blockDim.x;
    size_t i0 = (size_t)blockIdx.x * blockDim.x + threadIdx.x;
    const size_t WR_N = (size_t)SDIM * SDIM;
    const size_t W_N  = (size_t)JDIM * SDIM;
    for (size_t i = i0; i < W_N; i += stride) {
        float v = (i < WR_N) ? w_r[i] : w_o[i - WR_N];
        g_W[i] = __float2bfloat16(v);
    }
    for (size_t i = i0; i < (size_t)BATCH * SDIM; i += stride) {
        g_G[0][i] = __float2bfloat16(tanhf(h_init[i]));
    }
}

// ---------------- persistent kernel: group == cluster(16), mbarrier-only sync ----------------
__global__ void __launch_bounds__(NTHREADS, 1)
trnn_persistent(const float* __restrict__ x, const float* __restrict__ h_init,
                const float* __restrict__ b_r, const float* __restrict__ b_o,
                float* __restrict__ out) {
    extern __shared__ char smem[];
    __nv_bfloat16* sG = (__nv_bfloat16*)smem;
    __nv_bfloat16* sW = (__nv_bfloat16*)(smem + SG_BYTES);
    float* sP = (float*)(smem + SG_BYTES + SW_BYTES);
    const uint32_t mbBase = (uint32_t)__cvta_generic_to_shared(smem + SG_BYTES + SW_BYTES + SP_BYTES);
    const uint32_t mbarTile  = mbBase;       // expect_tx 32KB; 16 TMA sources
    const uint32_t mbarData  = mbBase + 8;   // 13 producer arrivals (G gmem ready)
    const uint32_t mbarReads = mbBase + 16;  // 16 arrivals (peers done reading sG)

    const int tid  = threadIdx.x;
    const int warp = tid >> 5;
    const int lane = tid & 31;
    const int grp  = lane >> 2;   // 0..7
    const int tig  = lane & 3;    // 0..3
    uint32_t rank;
    asm("mov.u32 %0, %%cluster_ctarank;" : "=r"(rank));   // == jtile, 0..15
    const int group = blockIdx.x >> 4;                    // 0..7
    const int b0 = group * GR;
    const int j0 = (int)rank * JT;
    const int kw = warp * KSLICE;
    const bool prodAny = (j0 < SDIM);                     // jtiles 0..12

    if (tid == 0) {
        asm volatile("mbarrier.init.shared.b64 [%0], 1;"  :: "r"(mbarTile)  : "memory");
        asm volatile("mbarrier.init.shared.b64 [%0], %1;" :: "r"(mbarData),  "r"(NPRODUCERS) : "memory");
        asm volatile("mbarrier.init.shared.b64 [%0], %1;" :: "r"(mbarReads), "r"(CLUSTER)    : "memory");
    }
    __syncthreads();
    asm volatile("barrier.cluster.arrive.aligned;" ::: "memory");
    asm volatile("barrier.cluster.wait.aligned;"   ::: "memory");

    // --- per-thread persistent epilogue state: e = d*256 + tid, exactly 1280 = 5*256 ---
    int ej[EPT]; int erow[EPT]; float hr[EPT]; float bv[EPT];
    #pragma unroll
    for (int d = 0; d < EPT; ++d) {
        int e = d * NTHREADS + tid;
        int r = e / JT, c = e - r * JT;
        int j = j0 + c;
        ej[d] = j; erow[d] = r;
        if (j < SDIM) {
            hr[d] = h_init[(size_t)(b0 + r) * SDIM + j];
            bv[d] = b_r[j];
        } else {
            hr[d] = 0.f;
            bv[d] = b_o[j - SDIM];
        }
    }

    // --- W cols [j0, j0+40): register-resident fragments (80 regs/thread) ---
    unsigned Breg[8][5][2];
    #pragma unroll
    for (int ks = 0; ks < 8; ++ks) {
        #pragma unroll
        for (int ni = 0; ni < 5; ++ni) {
            int jr = j0 + ni * 8 + grp;
            const unsigned* wp = (const unsigned*)(g_W + (size_t)jr * SDIM + kw + ks * 16);
            Breg[ks][ni][0] = wp[tig];
            Breg[ks][ni][1] = wp[4 + tig];
        }
    }
    // --- W cols [j0+40, j0+80): smem-resident (conflict-free 516-word stride) ---
    for (int i = tid; i < WROWS * (SDIM / 8); i += NTHREADS) {
        int r = i >> 7, c = i & 127;
        uint4 v = *(const uint4*)(g_W + (size_t)(j0 + 40 + r) * SDIM + c * 8);
        *(uint4*)(sW + r * GSTRIDE + c * 8) = v;
    }
    __syncthreads();

    const unsigned* sW32 = (const unsigned*)sW;
    const uint32_t sGb = (uint32_t)__cvta_generic_to_shared(sG);
    const int rl = lane & 15;
    const int khalf = (lane & 16) ? 8 : 0;
    const uint32_t aBase = sGb + (uint32_t)((rl * GSTRIDE + kw + khalf) * 2);

    for (int it = 0; it <= T_STEPS; ++it) {
        // --- x prefetch (off critical path) ---
        float xr[EPT];
        if (it >= 1) {
            #pragma unroll
            for (int d = 0; d < EPT; ++d)
                if (ej[d] >= SDIM) {
                    size_t oi = ((size_t)(it - 1) * BATCH + (b0 + erow[d])) * ODIM + (ej[d] - SDIM);
                    xr[d] = __ldcs(x + oi);
                }
        }

        // --- tid0: expect_tx, wait peer signals, issue 1-row multicast ---
        if (tid == 0) {
            asm volatile("mbarrier.arrive.expect_tx.shared.b64 _, [%0], %1;"
                         :: "r"(mbarTile), "r"(GR * ROW_BYTES) : "memory");
            if (it > 0) {
                const unsigned pprev = (unsigned)((it + 1) & 1);   // phase of step it-1
                mbar_wait_cl(mbarReads, pprev);   // all peers done reading sG
                mbar_wait_cl(mbarData,  pprev);   // all 13 producers' G stores visible
            }
            asm volatile("fence.proxy.async;" ::: "memory");
            const __nv_bfloat16* src = g_G[it & 1] + (size_t)(b0 + rank) * SDIM;
            uint32_t dst = sGb + rank * (GSTRIDE * 2);
            asm volatile(
                "cp.async.bulk.shared::cluster.global.mbarrier::complete_tx::bytes"
                ".multicast::cluster [%0], [%1], %2, [%3], %4;"
                :: "r"(dst), "l"((const void*)src), "r"(ROW_BYTES), "r"(mbarTile),
                   "h"((unsigned short)0xFFFF)
                : "memory");
        }

        // --- all warps: wait full 16-row tile, then mma ---
        mbar_wait(mbarTile, (unsigned)(it & 1));

        float acc[10][4];
        #pragma unroll
        for (int q = 0; q < 10; ++q)
            #pragma unroll
            for (int v = 0; v < 4; ++v) acc[q][v] = 0.f;

        #pragma unroll
        for (int ks = 0; ks < 8; ++ks) {
            unsigned a[4];
            ldsm_x4(a, aBase + ks * 32);
            const int kwrd = (kw >> 1) + ks * 8;
            #pragma unroll
            for (int ni = 0; ni < 5; ++ni)
                mma16816(acc[ni], a, Breg[ks][ni][0], Breg[ks][ni][1]);
            #pragma unroll
            for (int ni = 0; ni < 5; ++ni) {
                int rw = ni * 8 + grp;   // local sW row
                unsigned b0w = sW32[rw * (GSTRIDE / 2) + kwrd + tig];
                unsigned b1w = sW32[rw * (GSTRIDE / 2) + kwrd + 4 + tig];
                mma16816(acc[5 + ni], a, b0w, b1w);
            }
        }

        // --- per-warp partials: 16 rows x 80 cols ---
        {
            float* p = sP + warp * (GR * JT);
            #pragma unroll
            for (int q = 0; q < 10; ++q) {
                int cc = q * 8 + tig * 2;
                *(float2*)&p[grp * JT + cc]       = make_float2(acc[q][0], acc[q][1]);
                *(float2*)&p[(grp + 8) * JT + cc] = make_float2(acc[q][2], acc[q][3]);
            }
        }
        __syncthreads();   // sync1: partials in, all sG reads done

        // reads-done: enable peers' next TMA overwrite of my sG (16 parallel remote arrives)
        if (warp == 0 && lane < CLUSTER) mbar_arrive_remote(mbarReads, (uint32_t)lane);

        // --- split-K reduce + h update + tanh + G store ---
        __nv_bfloat16* Gn = g_G[(it + 1) & 1];
        float yv[EPT];
        #pragma unroll
        for (int d = 0; d < EPT; ++d) {
            int e = d * NTHREADS + tid;
            float y = sP[e];
            #pragma unroll
            for (int w = 1; w < NWARPS; ++w) y += sP[w * (GR * JT) + e];
            yv[d] = y;
            if (ej[d] < SDIM) {
                float hv = 0.75f * hr[d] + 0.25f * (y + bv[d]);
                hr[d] = hv;
                Gn[(size_t)(b0 + erow[d]) * SDIM + ej[d]] = __float2bfloat16(tanh_fast(hv));
            }
        }
        __syncthreads();   // sync2: all G stores done; also protects sP reuse next step

        // data-ready: producers signal all 16 peers (release.cluster orders the G stores)
        if (prodAny && warp == 0 && lane < CLUSTER)
            mbar_arrive_remote(mbarData, (uint32_t)lane);

        // --- outputs (off the critical path) ---
        if (it >= 1) {
            #pragma unroll
            for (int d = 0; d < EPT; ++d)
                if (ej[d] >= SDIM) {
                    size_t oi = ((size_t)(it - 1) * BATCH + (b0 + erow[d])) * ODIM + (ej[d] - SDIM);
                    out[oi] = yv[d] + bv[d] - xr[d];
                }
        }
    }

    // no CTA may exit while peers' multicast/arrives targeting its smem are possible
    asm volatile("barrier.cluster.arrive.aligned;" ::: "memory");
    asm volatile("barrier.cluster.wait.aligned;"   ::: "memory");
}

// ---------------- launch ----------------
extern "C" void kernel_launch(void* const* d_in, const int* in_sizes, int n_in,
                              void* d_out, int out_size) {
    const float *x = nullptr, *h = nullptr, *wr = nullptr, *br = nullptr,
                *wo = nullptr, *bo = nullptr;
    for (int i = 0; i < n_in; ++i) {
        switch (in_sizes[i]) {
            case 512 * 128 * 256: x  = (const float*)d_in[i]; break;
            case 128 * 1024:      h  = (const float*)d_in[i]; break;
            case 1024 * 1024:     wr = (const float*)d_in[i]; break;
            case 1024:            br = (const float*)d_in[i]; break;
            case 256 * 1024:      wo = (const float*)d_in[i]; break;
            case 256:             bo = (const float*)d_in[i]; break;
            default: break;
        }
    }
    cudaFuncSetAttribute(trnn_persistent,
                         cudaFuncAttributeMaxDynamicSharedMemorySize, SMEM_TOTAL);
    cudaFuncSetAttribute(trnn_persistent,
                         cudaFuncAttributeNonPortableClusterSizeAllowed, 1);

    trnn_init<<<512, 256>>>(wr, wo, h);

    cudaLaunchConfig_t cfg = {};
    cfg.gridDim = dim3(NCTAS, 1, 1);
    cfg.blockDim = dim3(NTHREADS, 1, 1);
    cfg.dynamicSmemBytes = SMEM_TOTAL;
    cfg.stream = 0;
    cudaLaunchAttribute attrs[1];
    attrs[0].id = cudaLaunchAttributeClusterDimension;
    attrs[0].val.clusterDim.x = CLUSTER;
    attrs[0].val.clusterDim.y = 1;
    attrs[0].val.clusterDim.z = 1;
    cfg.attrs = attrs;
    cfg.numAttrs = 1;
    cudaLaunchKernelEx(&cfg, trnn_persistent, x, h, br, bo, (float*)d_out);
}

// round 12
// speedup vs baseline: 1.5342x; 1.5342x over previous
#include <cuda_runtime.h>
#include <cuda_bf16.h>
#include <cuda_fp8.h>
#include <cstdint>

// ---------------- problem dims (fixed by dataset) ----------------
#define T_STEPS 512
#define BATCH   128
#define SDIM    1024
#define ODIM    256
#define JDIM    (SDIM + ODIM)   // 1280

// ---------------- tiling (R4 topology) ----------------
#define NB 4                 // batch tiles (independent recurrence groups)
#define NJ 32                // j tiles
#define BT 32                // batch rows per CTA
#define JT 40                // j cols per CTA
#define NCTAS (NB * NJ)      // 128 CTAs, one per SM
#define NTHREADS 256
#define NWARPS 8
#define CLUSTER 4
#define ROWS_PER_CTA (BT / CLUSTER)   // 8 rows loaded+multicast per CTA
#define NPROD 26             // jtiles 0..25 produce h columns
// fp8: K slice per warp = 256 (row-split: warps 0-3 rows 0-15, warps 4-7 rows 16-31)
#define KSL 256
#define ROW_BYTES 1024       // fp8 G row in gmem
#define GSTRIDE_B 1040       // smem row stride bytes (1024 + 16 pad)
#define EPT 5

// scaling: W stored x64, G stored x16, y_true = mma / 1024
#define Y_INV (1.0f / 1024.0f)

// smem layout (bytes)
#define SG_BYTES (BT * GSTRIDE_B)              // 33280
#define SP_BYTES (NWARPS * 16 * JT * 4)        // 20480
#define SMEM_TOTAL (SG_BYTES + SP_BYTES + 16)  // + two mbarriers

// ---------------- device globals ----------------
__device__ __align__(16) uint8_t g_W[(size_t)JDIM * SDIM];      // e4m3, x64
__device__ __align__(16) uint8_t g_G[2][(size_t)BATCH * SDIM];  // e4m3, tanh(h) x16
__device__ unsigned g_slots0[NB * 32];
__device__ unsigned g_slots1[NB * 32];

// ---------------- helpers ----------------
__device__ __forceinline__ unsigned ld_acq(const unsigned* p) {
    unsigned v;
    asm volatile("ld.acquire.gpu.global.u32 %0, [%1];" : "=r"(v) : "l"(p));
    return v;
}
__device__ __forceinline__ void st_rel(unsigned* p, unsigned v) {
    asm volatile("st.release.gpu.global.u32 [%0], %1;" :: "l"(p), "r"(v) : "memory");
}
__device__ __forceinline__ float tanh_fast(float v) {
    float r;
    asm("tanh.approx.f32 %0, %1;" : "=f"(r) : "f"(v));
    return r;
}
__device__ __forceinline__ uint8_t to_e4m3(float v) {
    return (uint8_t)__nv_cvt_float_to_fp8(v, __NV_SATFINITE, __NV_E4M3);
}
__device__ __forceinline__ void mma_fp8(float c[4], const unsigned a[4],
                                        unsigned b0, unsigned b1) {
    asm volatile(
        "mma.sync.aligned.m16n8k32.row.col.f32.e4m3.e4m3.f32 "
        "{%0,%1,%2,%3}, {%4,%5,%6,%7}, {%8,%9}, {%0,%1,%2,%3};\n"
        : "+f"(c[0]), "+f"(c[1]), "+f"(c[2]), "+f"(c[3])
        : "r"(a[0]), "r"(a[1]), "r"(a[2]), "r"(a[3]), "r"(b0), "r"(b1));
}
__device__ __forceinline__ void ldsm_x4(unsigned a[4], uint32_t addr) {
    asm volatile("ldmatrix.sync.aligned.m8n8.x4.shared.b16 {%0,%1,%2,%3}, [%4];"
                 : "=r"(a[0]), "=r"(a[1]), "=r"(a[2]), "=r"(a[3]) : "r"(addr));
}
__device__ __forceinline__ void mbar_wait(uint32_t mbar, unsigned parity) {
    asm volatile(
        "{\n\t"
        ".reg .pred P;\n\t"
        "WL_%=:\n\t"
        "mbarrier.try_wait.parity.acquire.cta.shared::cta.b64 P, [%0], %1, 0x989680;\n\t"
        "@P bra.uni WD_%=;\n\t"
        "bra.uni WL_%=;\n\t"
        "WD_%=:\n\t"
        "}" :: "r"(mbar), "r"(parity) : "memory");
}

// ---------------- init: fp8 weights (x64) + G0 = tanh(h_init) x16 ----------------
__global__ void trnn_init(const float* __restrict__ w_r, const float* __restrict__ w_o,
                          const float* __restrict__ h_init) {
    size_t stride = (size_t)gridDim.x * blockDim.x;
    size_t i0 = (size_t)blockIdx.x * blockDim.x + threadIdx.x;
    const size_t WR_N = (size_t)SDIM * SDIM;
    const size_t W_N  = (size_t)JDIM * SDIM;
    for (size_t i = i0; i < W_N; i += stride) {
        float v = (i < WR_N) ? w_r[i] : w_o[i - WR_N];
        g_W[i] = to_e4m3(v * 64.0f);
    }
    for (size_t i = i0; i < (size_t)BATCH * SDIM; i += stride) {
        g_G[0][i] = to_e4m3(tanhf(h_init[i]) * 16.0f);
    }
    if (i0 < NB * 32) { g_slots0[i0] = 0u; g_slots1[i0] = 0u; }
}

// ---------------- persistent kernel: R4 topology, fp8 operands, row-split warps ----------------
__global__ void __launch_bounds__(NTHREADS, 1) __cluster_dims__(CLUSTER, 1, 1)
trnn_persistent(const float* __restrict__ x, const float* __restrict__ h_init,
                const float* __restrict__ b_r, const float* __restrict__ b_o,
                float* __restrict__ out) {
    extern __shared__ char smem[];
    uint8_t* sG = (uint8_t*)smem;
    float* sP = (float*)(smem + SG_BYTES);
    uint32_t mbar0 = (uint32_t)__cvta_generic_to_shared(smem + SG_BYTES + SP_BYTES);
    uint32_t mbar1 = mbar0 + 8;

    const int tid  = threadIdx.x;
    const int warp = tid >> 5;
    const int lane = tid & 31;
    const int grp  = lane >> 2;   // 0..7
    const int tig  = lane & 3;    // 0..3
    const int btile = blockIdx.x >> 5;
    const int jtile = blockIdx.x & 31;
    const int rank  = blockIdx.x & (CLUSTER - 1);
    const int b0 = btile * BT;
    const int j0 = jtile * JT;
    const int wg = warp & 3;              // K quarter: [wg*256, wg*256+256)
    const int rowbase = (warp >> 2) * 16; // warps 0-3: rows 0-15; 4-7: rows 16-31
    const bool producer = (jtile < NPROD);

    unsigned* my_slots = (rank < 2) ? &g_slots0[btile * 32] : &g_slots1[btile * 32];
    unsigned* rel0 = &g_slots0[btile * 32 + jtile];
    unsigned* rel1 = &g_slots1[btile * 32 + jtile];
    const uint32_t my_mbar = (rank < 2) ? mbar0 : mbar1;       // TMA target (rows rank*8..)
    const uint32_t warp_mbar = (warp < 4) ? mbar0 : mbar1;     // tile half this warp reads

    if (tid == 0) {
        asm volatile("mbarrier.init.shared.b64 [%0], 1;" :: "r"(mbar0) : "memory");
        asm volatile("mbarrier.init.shared.b64 [%0], 1;" :: "r"(mbar1) : "memory");
    }
    __syncthreads();
    asm volatile("barrier.cluster.arrive.aligned;" ::: "memory");
    asm volatile("barrier.cluster.wait.aligned;"   ::: "memory");

    // --- per-thread persistent epilogue state (e = d*256 + tid over 1280) ---
    int ej[EPT]; int ebl[EPT]; float hr[EPT]; float bv[EPT];
    #pragma unroll
    for (int d = 0; d < EPT; ++d) {
        int e = d * NTHREADS + tid;
        int bl = e / JT, jl = e - bl * JT;
        int j = j0 + jl;
        ej[d] = j; ebl[d] = bl;
        if (j < SDIM) {
            hr[d] = h_init[(size_t)(b0 + bl) * SDIM + j];
            bv[d] = b_r[j];
        } else {
            hr[d] = 0.f;
            bv[d] = b_o[j - SDIM];
        }
    }

    // --- W fragments (fp8, x64) persistent in registers: 8 k32-steps x 5 n x 2 = 80 regs ---
    unsigned Breg[8][5][2];
    #pragma unroll
    for (int ks = 0; ks < 8; ++ks) {
        #pragma unroll
        for (int ni = 0; ni < 5; ++ni) {
            int jr = j0 + ni * 8 + grp;
            const unsigned* wp = (const unsigned*)(g_W + (size_t)jr * SDIM + wg * KSL + ks * 32);
            Breg[ks][ni][0] = wp[tig];       // bytes [tig*4, tig*4+4)
            Breg[ks][ni][1] = wp[4 + tig];   // bytes [16+tig*4, ...)
        }
    }
    __syncthreads();

    // --- ldmatrix base: 16 rows x 32B per k-step; fp8 k32 frag == bf16 k16 byte layout ---
    const uint32_t sGb = (uint32_t)__cvta_generic_to_shared(sG);
    const int rl = lane & 15;
    const uint32_t aBase = sGb + (uint32_t)((rowbase + rl) * GSTRIDE_B + wg * KSL
                                            + ((lane & 16) ? 16 : 0));

    for (int it = 0; it <= T_STEPS; ++it) {
        const unsigned parity = (unsigned)(it & 1);

        // --- expect_tx for both half-tiles (prev phases done via last sync) ---
        if (tid == 0) {
            asm volatile("mbarrier.arrive.expect_tx.shared.b64 _, [%0], %1;"
                         :: "r"(mbar0), "r"(16 * ROW_BYTES) : "memory");
            asm volatile("mbarrier.arrive.expect_tx.shared.b64 _, [%0], %1;"
                         :: "r"(mbar1), "r"(16 * ROW_BYTES) : "memory");
        }

        // --- x prefetch (off critical path) ---
        float xr[EPT];
        if (it >= 1) {
            #pragma unroll
            for (int d = 0; d < EPT; ++d)
                if (ej[d] >= SDIM) {
                    size_t oi = ((size_t)(it - 1) * BATCH + (b0 + ebl[d])) * ODIM + (ej[d] - SDIM);
                    xr[d] = __ldcs(x + oi);
                }
        }

        // --- warp0 polls the slot-set gating THIS rank's rows ---
        if (it > 0 && warp == 0) {
            const unsigned phase = (unsigned)it;
            for (;;) {
                unsigned v = ld_acq(&my_slots[lane]);
                if (__all_sync(0xffffffffu, v >= phase)) break;
            }
        }

        // --- tid0: issue 8 multicast row-copies (1KB each) to this rank's half-mbar ---
        if (tid == 0) {
            const uint8_t* Gc = g_G[it & 1];
            asm volatile("fence.proxy.async;" ::: "memory");
            #pragma unroll
            for (int rr = 0; rr < ROWS_PER_CTA; ++rr) {
                int r = rank * ROWS_PER_CTA + rr;
                const void* src = (const void*)(Gc + (size_t)(b0 + r) * SDIM);
                uint32_t dst = sGb + (uint32_t)(r * GSTRIDE_B);
                asm volatile(
                    "cp.async.bulk.shared::cluster.global.mbarrier::complete_tx::bytes"
                    ".multicast::cluster [%0], [%1], %2, [%3], %4;"
                    :: "r"(dst), "l"(src), "r"(ROW_BYTES), "r"(my_mbar),
                       "h"((unsigned short)((1u << CLUSTER) - 1u))
                    : "memory");
            }
        }

        // --- wait ONLY this warp's row-half, then full-K-quarter mma (40 mma) ---
        mbar_wait(warp_mbar, parity);

        float acc[5][4];
        #pragma unroll
        for (int ni = 0; ni < 5; ++ni)
            #pragma unroll
            for (int q = 0; q < 4; ++q) acc[ni][q] = 0.f;

        #pragma unroll
        for (int ks = 0; ks < 8; ++ks) {
            unsigned a[4];
            ldsm_x4(a, aBase + ks * 32);
            #pragma unroll
            for (int ni = 0; ni < 5; ++ni)
                mma_fp8(acc[ni], a, Breg[ks][ni][0], Breg[ks][ni][1]);
        }

        // --- per-warp partials: 16 x 40 tile in slot `warp` ---
        {
            float* p = sP + warp * (16 * JT);
            #pragma unroll
            for (int ni = 0; ni < 5; ++ni) {
                int cc = ni * 8 + tig * 2;
                *(float2*)&p[grp * JT + cc]       = make_float2(acc[ni][0], acc[ni][1]);
                *(float2*)&p[(grp + 8) * JT + cc] = make_float2(acc[ni][2], acc[ni][3]);
            }
        }
        __syncthreads();   // sync1: partials in, all sG reads done

        // consumer-only CTAs: arrive early (off critical path)
        if (!producer && tid == 0) {
            st_rel(rel0, (unsigned)(it + 1));
            st_rel(rel1, (unsigned)(it + 1));
        }

        // --- 4-partial reduce + h update + tanh + fp8 G store ---
        uint8_t* Gn = g_G[(it + 1) & 1];
        float yv[EPT];
        #pragma unroll
        for (int d = 0; d < EPT; ++d) {
            int e = d * NTHREADS + tid;
            int base = (e < 640) ? e : e + 1920;   // rows<16: slots 0-3; rows>=16: slots 4-7
            float y = (sP[base] + sP[base + 640]) + (sP[base + 1280] + sP[base + 1920]);
            float ys = y * Y_INV;
            yv[d] = ys;
            if (ej[d] < SDIM) {
                float hv = 0.75f * hr[d] + 0.25f * (ys + bv[d]);
                hr[d] = hv;
                Gn[(size_t)(b0 + ebl[d]) * SDIM + ej[d]] = to_e4m3(tanh_fast(hv) * 16.0f);
            }
        }
        __syncthreads();   // sync2: G stores done; also protects sP reuse (fixes latent race)

        if (producer && tid == 0) {
            st_rel(rel0, (unsigned)(it + 1));
            st_rel(rel1, (unsigned)(it + 1));
        }

        // --- outputs (off the critical path) ---
        if (it >= 1) {
            #pragma unroll
            for (int d = 0; d < EPT; ++d)
                if (ej[d] >= SDIM) {
                    size_t oi = ((size_t)(it - 1) * BATCH + (b0 + ebl[d])) * ODIM + (ej[d] - SDIM);
                    out[oi] = yv[d] + bv[d] - xr[d];
                }
        }
    }

    asm volatile("barrier.cluster.arrive.aligned;" ::: "memory");
    asm volatile("barrier.cluster.wait.aligned;"   ::: "memory");
}

// ---------------- launch ----------------
extern "C" void kernel_launch(void* const* d_in, const int* in_sizes, int n_in,
                              void* d_out, int out_size) {
    const float *x = nullptr, *h = nullptr, *wr = nullptr, *br = nullptr,
                *wo = nullptr, *bo = nullptr;
    for (int i = 0; i < n_in; ++i) {
        switch (in_sizes[i]) {
            case 512 * 128 * 256: x  = (const float*)d_in[i]; break;
            case 128 * 1024:      h  = (const float*)d_in[i]; break;
            case 1024 * 1024:     wr = (const float*)d_in[i]; break;
            case 1024:            br = (const float*)d_in[i]; break;
            case 256 * 1024:      wo = (const float*)d_in[i]; break;
            case 256:             bo = (const float*)d_in[i]; break;
            default: break;
        }
    }
    cudaFuncSetAttribute(trnn_persistent,
                         cudaFuncAttributeMaxDynamicSharedMemorySize, SMEM_TOTAL);
    trnn_init<<<512, 256>>>(wr, wo, h);
    trnn_persistent<<<NCTAS, NTHREADS, SMEM_TOTAL>>>(x, h, br, bo, (float*)d_out);
}